// round 12
// baseline (speedup 1.0000x reference)
#include <cuda_runtime.h>
#include <cuda_fp16.h>
#include <cstdint>

// DepthAwareTokenAggregator via mma.sync fp16 (sm_80 ISA).
// B=8, N=512, Y=64, C=256. 2 tokens/CTA: M=128, K=256, N=256 (2 passes of 128).
// 512 threads (16 warps, 32x32 warp tile), 2 CTAs/SM.
// R9 structure exactly; single change: fast A&S-7.1.26 gelu.

#define Yd 64
#define Cd 256
#define THREADS 512
#define CTAS 2048

// ---- smem byte offsets ----
#define SM_YN    0        // 64 f32
#define SM_B1    256      // 256 f32
#define SM_W2    1280     // 256 f32
#define SM_W1L   2304     // 256 f32 (W1 row 256: y_norm feature row)
#define SM_LP    3328     // 4 x 128 f32 logit partials
#define SM_LOG   5376     // 128 f32
#define SM_WGT   5888     // 128 f32
#define SM_A     6400     // 128 rows x 264 fp16 (stride 528B) = 67584
#define SM_B     73984    // 2 bufs x 18432 (128 n x 72 k fp16, stride 144B)
#define SMEM_TOTAL 110848

#define A_STRIDE 528
#define B_STRIDE 144      // 64 fp16 (128B) + 16B pad
#define BCHUNK   18432

// prepacked W1 fp16: [2 pass][4 chunk][128 n][64 k]
__device__ __half w1pack[2 * 4 * 128 * 64];

static __device__ __forceinline__ uint32_t smem_u32(const void* p) {
    uint32_t a;
    asm("{ .reg .u64 t; cvta.to.shared.u64 t, %1; cvt.u32.u64 %0, t; }" : "=r"(a) : "l"(p));
    return a;
}

static __device__ __forceinline__ void ldsm4(uint32_t* r, uint32_t addr) {
    asm volatile("ldmatrix.sync.aligned.m8n8.x4.shared.b16 {%0,%1,%2,%3}, [%4];"
                 : "=r"(r[0]), "=r"(r[1]), "=r"(r[2]), "=r"(r[3]) : "r"(addr));
}

static __device__ __forceinline__ void mma16816(float* d, const uint32_t* a,
                                                uint32_t b0, uint32_t b1) {
    asm volatile(
        "mma.sync.aligned.m16n8k16.row.col.f32.f16.f16.f32 "
        "{%0,%1,%2,%3}, {%4,%5,%6,%7}, {%8,%9}, {%0,%1,%2,%3};"
        : "+f"(d[0]), "+f"(d[1]), "+f"(d[2]), "+f"(d[3])
        : "r"(a[0]), "r"(a[1]), "r"(a[2]), "r"(a[3]), "r"(b0), "r"(b1));
}

#define CP_ASYNC16(dst, src) \
    asm volatile("cp.async.cg.shared.global [%0], [%1], 16;" :: "r"(dst), "l"(src) : "memory")
#define CP_COMMIT() asm volatile("cp.async.commit_group;" ::: "memory")
#define CP_WAIT1()  asm volatile("cp.async.wait_group 1;" ::: "memory")
#define CP_WAIT0()  asm volatile("cp.async.wait_group 0;" ::: "memory")

// gelu via A&S 7.1.26 rational erf: |abs err| <= 1.5e-7, ~15 issues (2 MUFU)
static __device__ __forceinline__ float gelu_fast(float x) {
    const float z  = x * 0.70710678118654752440f;
    const float az = fabsf(z);
    const float t  = __frcp_rn(fmaf(0.3275911f, az, 1.0f));
    float p = fmaf(1.061405429f, t, -1.453152027f);
    p = fmaf(p, t, 1.421413741f);
    p = fmaf(p, t, -0.284496736f);
    p = fmaf(p, t, 0.254829592f);
    p = p * t;
    const float e = __expf(-z * z);
    float erf_abs = fmaf(-p, e, 1.0f);
    float erfv = copysignf(erf_abs, z);
    return 0.5f * x * (1.0f + erfv);
}

// ---- pre-kernel: pack W1 (f32 [257,256]) -> fp16 chunk blocks ----
__global__ void pack_w1_kernel(const float* __restrict__ W1) {
    int gid = blockIdx.x * blockDim.x + threadIdx.x;   // 0..16383
    #pragma unroll
    for (int it = 0; it < 4; it++) {
        int e = gid + it * 16384;                      // 0..65535
        int p = e >> 15;
        int rem = e & 32767;
        int k = rem >> 7;                              // 0..255
        int n = rem & 127;
        int c = k >> 6, kk = k & 63;
        float x = W1[(size_t)k * Cd + p * 128 + n];
        w1pack[(size_t)(p * 4 + c) * 8192 + n * 64 + kk] = __float2half_rn(x);
    }
}

static __device__ __forceinline__ void issue_chunk(uint32_t sbase, int tid, int i) {
    const uint32_t dstb = sbase + SM_B + (i & 1) * BCHUNK;
    const __half* srcb = w1pack + (size_t)i * 8192;
    #pragma unroll
    for (int j = 0; j < 2; j++) {
        int idx16 = tid * 2 + j;                       // 0..1023
        int n = idx16 >> 3, ko = idx16 & 7;
        uint32_t dst = dstb + n * B_STRIDE + ko * 16;
        const void* src = srcb + idx16 * 8;
        CP_ASYNC16(dst, src);
    }
}

static __device__ __forceinline__ void epilogue_pass(
    float acc[2][4][4], float* lp, int p, const char* smem, int lane, int m0, int n0w)
{
    const float* b1s  = (const float*)(smem + SM_B1);
    const float* w2s  = (const float*)(smem + SM_W2);
    const float* w1ls = (const float*)(smem + SM_W1L);
    const float* yns  = (const float*)(smem + SM_YN);
    float yl[8], bb[8], ww[8];
    #pragma unroll
    for (int nt = 0; nt < 4; nt++)
        #pragma unroll
        for (int eb = 0; eb < 2; eb++) {
            int n = p * 128 + n0w + nt * 8 + 2 * (lane & 3) + eb;
            yl[nt * 2 + eb] = w1ls[n];
            bb[nt * 2 + eb] = b1s[n];
            ww[nt * 2 + eb] = w2s[n];
        }
    #pragma unroll
    for (int mt = 0; mt < 2; mt++)
        #pragma unroll
        for (int h = 0; h < 2; h++) {
            int row = m0 + mt * 16 + h * 8 + (lane >> 2);
            float yn = yns[row & 63];
            float s = 0.f;
            #pragma unroll
            for (int nt = 0; nt < 4; nt++)
                #pragma unroll
                for (int eb = 0; eb < 2; eb++) {
                    float x = acc[mt][nt][h * 2 + eb] + yn * yl[nt * 2 + eb] + bb[nt * 2 + eb];
                    s += gelu_fast(x) * ww[nt * 2 + eb];
                }
            lp[mt * 2 + h] += s;
        }
}

__global__ __launch_bounds__(THREADS, 2)
void dat_mma6_kernel(const float* __restrict__ sampled,
                     const float* __restrict__ valid,
                     const float* __restrict__ y_norm,
                     const float* __restrict__ W1,
                     const float* __restrict__ b1,
                     const float* __restrict__ W2,
                     const float* __restrict__ b2,
                     float* __restrict__ out)
{
    extern __shared__ char smem[];
    const uint32_t sbase = smem_u32(smem);
    const int tid  = threadIdx.x;
    const int wid  = tid >> 5;
    const int lane = tid & 31;
    const int bn2  = blockIdx.x;

    // warp tile: wm in {0..3} -> 32 m-rows, wn in {0..3} -> 32 n-cols
    const int wm = wid & 3, wn = wid >> 2;
    const int m0 = wm * 32, n0w = wn * 32;

    // B pipeline first so cp.async overlaps the A load/convert
    issue_chunk(sbase, tid, 0); CP_COMMIT();
    issue_chunk(sbase, tid, 1); CP_COMMIT();

    // small vectors
    if (tid < Yd) ((float*)(smem + SM_YN))[tid] = y_norm[tid];
    if (tid < Cd) {
        ((float*)(smem + SM_B1))[tid]  = b1[tid];
        ((float*)(smem + SM_W2))[tid]  = W2[tid];
        ((float*)(smem + SM_W1L))[tid] = W1[(size_t)Cd * Cd + tid];
    }

    // ---- A: 128 rows x 256 f32 -> fp16, padded row-major; affine pointers ----
    {
        const float4* src = (const float4*)(sampled + (size_t)bn2 * (2 * Yd * Cd)) + tid;
        char* dst = smem + SM_A + (tid >> 6) * A_STRIDE + (tid & 63) * 8;
        #pragma unroll
        for (int i = 0; i < 16; i++) {
            float4 v = *src;
            __half2 h01 = __floats2half2_rn(v.x, v.y);
            __half2 h23 = __floats2half2_rn(v.z, v.w);
            *(uint2*)dst = make_uint2(*(uint32_t*)&h01, *(uint32_t*)&h23);
            src += THREADS;
            dst += 8 * A_STRIDE;   // 512 threads cover 8 rows per step
        }
    }

    float acc[2][4][4];
    #pragma unroll
    for (int mt = 0; mt < 2; mt++)
        #pragma unroll
        for (int nt = 0; nt < 4; nt++)
            #pragma unroll
            for (int e = 0; e < 4; e++) acc[mt][nt][e] = 0.f;
    float lp[4] = {0.f, 0.f, 0.f, 0.f};

    // hoisted smem bases
    const uint32_t abase = sbase + SM_A
        + (uint32_t)((m0 + (lane & 15)) * A_STRIDE + ((lane & 16) >> 1) * 2);
    const uint32_t blane = (uint32_t)((n0w + (lane & 7) + ((lane & 16) >> 1)) * B_STRIDE
                                      + (lane & 8) * 2);

    // ---- main loop: 8 chunks (pass = i>>2, k-chunk = i&3, 64 k each) ----
    #pragma unroll
    for (int i = 0; i < 8; i++) {
        if (i < 7) { CP_WAIT1(); } else { CP_WAIT0(); }
        __syncthreads();

        const uint32_t buf = sbase + SM_B + (i & 1) * BCHUNK + blane;
        const int kbase = (i & 3) * 64;

        #pragma unroll
        for (int kk = 0; kk < 4; kk++) {
            const int kglob = kbase + kk * 16;
            uint32_t a_[2][4];
            ldsm4(a_[0], abase + kglob * 2);
            ldsm4(a_[1], abase + kglob * 2 + 16 * A_STRIDE);
            uint32_t bf[2][4];
            ldsm4(bf[0], buf + kk * 32);
            ldsm4(bf[1], buf + kk * 32 + 16 * B_STRIDE);
            #pragma unroll
            for (int mt = 0; mt < 2; mt++)
                #pragma unroll
                for (int q = 0; q < 2; q++)
                    #pragma unroll
                    for (int h = 0; h < 2; h++)
                        mma16816(acc[mt][q * 2 + h], a_[mt], bf[q][2 * h], bf[q][2 * h + 1]);
        }

        if (i == 3) {
            epilogue_pass(acc, lp, 0, smem, lane, m0, n0w);
            #pragma unroll
            for (int mt = 0; mt < 2; mt++)
                #pragma unroll
                for (int nt = 0; nt < 4; nt++)
                    #pragma unroll
                    for (int e = 0; e < 4; e++) acc[mt][nt][e] = 0.f;
        }
        __syncthreads();
        if (i + 2 < 8) { issue_chunk(sbase, tid, i + 2); CP_COMMIT(); }
    }
    epilogue_pass(acc, lp, 1, smem, lane, m0, n0w);

    // ---- reduce logits across the 4 lanes sharing a row, write per-wn partials ----
    #pragma unroll
    for (int i = 0; i < 4; i++) {
        lp[i] += __shfl_xor_sync(0xffffffffu, lp[i], 1);
        lp[i] += __shfl_xor_sync(0xffffffffu, lp[i], 2);
    }
    if ((lane & 3) == 0) {
        #pragma unroll
        for (int mt = 0; mt < 2; mt++)
            #pragma unroll
            for (int h = 0; h < 2; h++) {
                int row = m0 + mt * 16 + h * 8 + (lane >> 2);
                ((float*)(smem + SM_LP))[wn * 128 + row] = lp[mt * 2 + h];
            }
    }
    __syncthreads();

    if (tid < 128) {
        const float* lps = (const float*)(smem + SM_LP);
        ((float*)(smem + SM_LOG))[tid] =
            lps[tid] + lps[128 + tid] + lps[256 + tid] + lps[384 + tid] + __ldg(b2);
    }
    __syncthreads();

    // ---- masked softmax: warp 0 -> token 0, warp 1 -> token 1 ----
    if (wid < 2) {
        const int tk = wid;
        const float* logit = (const float*)(smem + SM_LOG);
        const float v0 = valid[(size_t)(bn2 * 2 + tk) * Yd + lane];
        const float v1 = valid[(size_t)(bn2 * 2 + tk) * Yd + lane + 32];
        float l0 = (v0 < 0.5f) ? -10000.0f : logit[tk * 64 + lane];
        float l1 = (v1 < 0.5f) ? -10000.0f : logit[tk * 64 + lane + 32];

        float m = fmaxf(l0, l1);
        #pragma unroll
        for (int off = 16; off > 0; off >>= 1)
            m = fmaxf(m, __shfl_xor_sync(0xffffffffu, m, off));
        float e0 = expf(l0 - m), e1 = expf(l1 - m);
        float s = e0 + e1;
        #pragma unroll
        for (int off = 16; off > 0; off >>= 1)
            s += __shfl_xor_sync(0xffffffffu, s, off);
        float p0 = (e0 / s) * v0;
        float p1 = (e1 / s) * v1;
        float s2 = p0 + p1;
        #pragma unroll
        for (int off = 16; off > 0; off >>= 1)
            s2 += __shfl_xor_sync(0xffffffffu, s2, off);
        const float inv = 1.0f / fmaxf(s2, 1e-6f);
        ((float*)(smem + SM_WGT))[tk * 64 + lane]      = p0 * inv;
        ((float*)(smem + SM_WGT))[tk * 64 + lane + 32] = p1 * inv;
    }
    __syncthreads();

    // ---- aggregation: one output element per thread; re-read sampled f32 (L2-hot) ----
    {
        const float* wgt = (const float*)(smem + SM_WGT) + (tid >> 8) * 64;
        const int t = tid >> 8, c = tid & 255;
        const float* sp = sampled + ((size_t)(bn2 * 2 + t) * Yd) * Cd + c;
        float o = 0.f;
        #pragma unroll 8
        for (int y = 0; y < Yd; y++)
            o = fmaf(wgt[y], sp[(size_t)y * Cd], o);
        out[(size_t)(bn2 * 2 + t) * Cd + c] = o;
    }
}

extern "C" void kernel_launch(void* const* d_in, const int* in_sizes, int n_in,
                              void* d_out, int out_size)
{
    const float* sampled = (const float*)d_in[0];
    const float* valid   = (const float*)d_in[1];
    const float* y_norm  = (const float*)d_in[2];
    const float* W1      = (const float*)d_in[3];
    const float* b1      = (const float*)d_in[4];
    const float* W2      = (const float*)d_in[5];
    const float* b2      = (const float*)d_in[6];
    float* out = (float*)d_out;

    pack_w1_kernel<<<64, 256>>>(W1);
    cudaFuncSetAttribute(dat_mma6_kernel, cudaFuncAttributeMaxDynamicSharedMemorySize, SMEM_TOTAL);
    dat_mma6_kernel<<<CTAS, THREADS, SMEM_TOTAL>>>(sampled, valid, y_norm, W1, b1, W2, b2, out);
}

// round 13
// speedup vs baseline: 1.6699x; 1.6699x over previous
#include <cuda_runtime.h>
#include <cuda_fp16.h>
#include <cstdint>

// DepthAwareTokenAggregator via mma.sync fp16 (sm_80 ISA).
// B=8, N=512, Y=64, C=256. 2 tokens/CTA: M=128, K=256, N=256 (2 passes of 128).
// 512 threads (16 warps, 32x32 warp tile), 2 CTAs/SM.
// R9 structure; fast A&S gelu with register-lean epilogue (params from smem).

#define Yd 64
#define Cd 256
#define THREADS 512
#define CTAS 2048

// ---- smem byte offsets ----
#define SM_YN    0        // 64 f32
#define SM_B1    256      // 256 f32
#define SM_W2    1280     // 256 f32
#define SM_W1L   2304     // 256 f32 (W1 row 256: y_norm feature row)
#define SM_LP    3328     // 4 x 128 f32 logit partials
#define SM_LOG   5376     // 128 f32
#define SM_WGT   5888     // 128 f32
#define SM_A     6400     // 128 rows x 264 fp16 (stride 528B) = 67584
#define SM_B     73984    // 2 bufs x 18432 (128 n x 72 k fp16, stride 144B)
#define SMEM_TOTAL 110848

#define A_STRIDE 528
#define B_STRIDE 144      // 64 fp16 (128B) + 16B pad
#define BCHUNK   18432

// prepacked W1 fp16: [2 pass][4 chunk][128 n][64 k]
__device__ __half w1pack[2 * 4 * 128 * 64];

static __device__ __forceinline__ uint32_t smem_u32(const void* p) {
    uint32_t a;
    asm("{ .reg .u64 t; cvta.to.shared.u64 t, %1; cvt.u32.u64 %0, t; }" : "=r"(a) : "l"(p));
    return a;
}

static __device__ __forceinline__ void ldsm4(uint32_t* r, uint32_t addr) {
    asm volatile("ldmatrix.sync.aligned.m8n8.x4.shared.b16 {%0,%1,%2,%3}, [%4];"
                 : "=r"(r[0]), "=r"(r[1]), "=r"(r[2]), "=r"(r[3]) : "r"(addr));
}

static __device__ __forceinline__ void mma16816(float* d, const uint32_t* a,
                                                uint32_t b0, uint32_t b1) {
    asm volatile(
        "mma.sync.aligned.m16n8k16.row.col.f32.f16.f16.f32 "
        "{%0,%1,%2,%3}, {%4,%5,%6,%7}, {%8,%9}, {%0,%1,%2,%3};"
        : "+f"(d[0]), "+f"(d[1]), "+f"(d[2]), "+f"(d[3])
        : "r"(a[0]), "r"(a[1]), "r"(a[2]), "r"(a[3]), "r"(b0), "r"(b1));
}

#define CP_ASYNC16(dst, src) \
    asm volatile("cp.async.cg.shared.global [%0], [%1], 16;" :: "r"(dst), "l"(src) : "memory")
#define CP_COMMIT() asm volatile("cp.async.commit_group;" ::: "memory")
#define CP_WAIT1()  asm volatile("cp.async.wait_group 1;" ::: "memory")
#define CP_WAIT0()  asm volatile("cp.async.wait_group 0;" ::: "memory")

// gelu via A&S 7.1.26 rational erf: |abs err| <= 1.5e-7
static __device__ __forceinline__ float gelu_fast(float x) {
    const float z  = x * 0.70710678118654752440f;
    const float az = fabsf(z);
    const float t  = __frcp_rn(fmaf(0.3275911f, az, 1.0f));
    float p = fmaf(1.061405429f, t, -1.453152027f);
    p = fmaf(p, t, 1.421413741f);
    p = fmaf(p, t, -0.284496736f);
    p = fmaf(p, t, 0.254829592f);
    p = p * t;
    const float e = __expf(-z * z);
    float erf_abs = fmaf(-p, e, 1.0f);
    float erfv = copysignf(erf_abs, z);
    return 0.5f * x * (1.0f + erfv);
}

// ---- pre-kernel: pack W1 (f32 [257,256]) -> fp16 chunk blocks ----
__global__ void pack_w1_kernel(const float* __restrict__ W1) {
    int gid = blockIdx.x * blockDim.x + threadIdx.x;   // 0..16383
    #pragma unroll
    for (int it = 0; it < 4; it++) {
        int e = gid + it * 16384;                      // 0..65535
        int p = e >> 15;
        int rem = e & 32767;
        int k = rem >> 7;                              // 0..255
        int n = rem & 127;
        int c = k >> 6, kk = k & 63;
        float x = W1[(size_t)k * Cd + p * 128 + n];
        w1pack[(size_t)(p * 4 + c) * 8192 + n * 64 + kk] = __float2half_rn(x);
    }
}

static __device__ __forceinline__ void issue_chunk(uint32_t sbase, int tid, int i) {
    const uint32_t dstb = sbase + SM_B + (i & 1) * BCHUNK;
    const __half* srcb = w1pack + (size_t)i * 8192;
    #pragma unroll
    for (int j = 0; j < 2; j++) {
        int idx16 = tid * 2 + j;                       // 0..1023
        int n = idx16 >> 3, ko = idx16 & 7;
        uint32_t dst = dstb + n * B_STRIDE + ko * 16;
        const void* src = srcb + idx16 * 8;
        CP_ASYNC16(dst, src);
    }
}

// Register-lean epilogue: per-n parameters read from smem (broadcast LDS)
// instead of preloaded register arrays -> keeps gelu_fast under the 64-reg cap.
static __device__ __forceinline__ void epilogue_pass(
    float acc[2][4][4], float* lp, int p, const char* smem, int lane, int m0, int n0w)
{
    const int nb = p * 128 + n0w + 2 * (lane & 3);
    const float* b1s  = (const float*)(smem + SM_B1)  + nb;
    const float* w2s  = (const float*)(smem + SM_W2)  + nb;
    const float* w1ls = (const float*)(smem + SM_W1L) + nb;
    const float* yns  = (const float*)(smem + SM_YN);
    #pragma unroll
    for (int mt = 0; mt < 2; mt++)
        #pragma unroll
        for (int h = 0; h < 2; h++) {
            int row = m0 + mt * 16 + h * 8 + (lane >> 2);
            float yn = yns[row & 63];
            float s = 0.f;
            #pragma unroll
            for (int nt = 0; nt < 4; nt++)
                #pragma unroll
                for (int eb = 0; eb < 2; eb++) {
                    int n8 = nt * 8 + eb;
                    float x = acc[mt][nt][h * 2 + eb] + fmaf(yn, w1ls[n8], b1s[n8]);
                    s += gelu_fast(x) * w2s[n8];
                }
            lp[mt * 2 + h] += s;
        }
}

__global__ __launch_bounds__(THREADS, 2)
void dat_mma7_kernel(const float* __restrict__ sampled,
                     const float* __restrict__ valid,
                     const float* __restrict__ y_norm,
                     const float* __restrict__ W1,
                     const float* __restrict__ b1,
                     const float* __restrict__ W2,
                     const float* __restrict__ b2,
                     float* __restrict__ out)
{
    extern __shared__ char smem[];
    const uint32_t sbase = smem_u32(smem);
    const int tid  = threadIdx.x;
    const int wid  = tid >> 5;
    const int lane = tid & 31;
    const int bn2  = blockIdx.x;

    // warp tile: wm in {0..3} -> 32 m-rows, wn in {0..3} -> 32 n-cols
    const int wm = wid & 3, wn = wid >> 2;
    const int m0 = wm * 32, n0w = wn * 32;

    // B pipeline first so cp.async overlaps the A load/convert
    issue_chunk(sbase, tid, 0); CP_COMMIT();
    issue_chunk(sbase, tid, 1); CP_COMMIT();

    // small vectors
    if (tid < Yd) ((float*)(smem + SM_YN))[tid] = y_norm[tid];
    if (tid < Cd) {
        ((float*)(smem + SM_B1))[tid]  = b1[tid];
        ((float*)(smem + SM_W2))[tid]  = W2[tid];
        ((float*)(smem + SM_W1L))[tid] = W1[(size_t)Cd * Cd + tid];
    }

    // ---- A: 128 rows x 256 f32 -> fp16, padded row-major; affine pointers ----
    {
        const float4* src = (const float4*)(sampled + (size_t)bn2 * (2 * Yd * Cd)) + tid;
        char* dst = smem + SM_A + (tid >> 6) * A_STRIDE + (tid & 63) * 8;
        #pragma unroll
        for (int i = 0; i < 16; i++) {
            float4 v = *src;
            __half2 h01 = __floats2half2_rn(v.x, v.y);
            __half2 h23 = __floats2half2_rn(v.z, v.w);
            *(uint2*)dst = make_uint2(*(uint32_t*)&h01, *(uint32_t*)&h23);
            src += THREADS;
            dst += 8 * A_STRIDE;   // 512 threads cover 8 rows per step
        }
    }

    float acc[2][4][4];
    #pragma unroll
    for (int mt = 0; mt < 2; mt++)
        #pragma unroll
        for (int nt = 0; nt < 4; nt++)
            #pragma unroll
            for (int e = 0; e < 4; e++) acc[mt][nt][e] = 0.f;
    float lp[4] = {0.f, 0.f, 0.f, 0.f};

    // hoisted smem bases
    const uint32_t abase = sbase + SM_A
        + (uint32_t)((m0 + (lane & 15)) * A_STRIDE + ((lane & 16) >> 1) * 2);
    const uint32_t blane = (uint32_t)((n0w + (lane & 7) + ((lane & 16) >> 1)) * B_STRIDE
                                      + (lane & 8) * 2);

    // ---- main loop: 8 chunks (pass = i>>2, k-chunk = i&3, 64 k each) ----
    #pragma unroll
    for (int i = 0; i < 8; i++) {
        if (i < 7) { CP_WAIT1(); } else { CP_WAIT0(); }
        __syncthreads();

        const uint32_t buf = sbase + SM_B + (i & 1) * BCHUNK + blane;
        const int kbase = (i & 3) * 64;

        #pragma unroll
        for (int kk = 0; kk < 4; kk++) {
            const int kglob = kbase + kk * 16;
            uint32_t a_[2][4];
            ldsm4(a_[0], abase + kglob * 2);
            ldsm4(a_[1], abase + kglob * 2 + 16 * A_STRIDE);
            uint32_t bf[2][4];
            ldsm4(bf[0], buf + kk * 32);
            ldsm4(bf[1], buf + kk * 32 + 16 * B_STRIDE);
            #pragma unroll
            for (int mt = 0; mt < 2; mt++)
                #pragma unroll
                for (int q = 0; q < 2; q++)
                    #pragma unroll
                    for (int h = 0; h < 2; h++)
                        mma16816(acc[mt][q * 2 + h], a_[mt], bf[q][2 * h], bf[q][2 * h + 1]);
        }

        if (i == 3) {
            epilogue_pass(acc, lp, 0, smem, lane, m0, n0w);
            #pragma unroll
            for (int mt = 0; mt < 2; mt++)
                #pragma unroll
                for (int nt = 0; nt < 4; nt++)
                    #pragma unroll
                    for (int e = 0; e < 4; e++) acc[mt][nt][e] = 0.f;
        }
        __syncthreads();
        if (i + 2 < 8) { issue_chunk(sbase, tid, i + 2); CP_COMMIT(); }
    }
    epilogue_pass(acc, lp, 1, smem, lane, m0, n0w);

    // ---- reduce logits across the 4 lanes sharing a row, write per-wn partials ----
    #pragma unroll
    for (int i = 0; i < 4; i++) {
        lp[i] += __shfl_xor_sync(0xffffffffu, lp[i], 1);
        lp[i] += __shfl_xor_sync(0xffffffffu, lp[i], 2);
    }
    if ((lane & 3) == 0) {
        #pragma unroll
        for (int mt = 0; mt < 2; mt++)
            #pragma unroll
            for (int h = 0; h < 2; h++) {
                int row = m0 + mt * 16 + h * 8 + (lane >> 2);
                ((float*)(smem + SM_LP))[wn * 128 + row] = lp[mt * 2 + h];
            }
    }
    __syncthreads();

    if (tid < 128) {
        const float* lps = (const float*)(smem + SM_LP);
        ((float*)(smem + SM_LOG))[tid] =
            lps[tid] + lps[128 + tid] + lps[256 + tid] + lps[384 + tid] + __ldg(b2);
    }
    __syncthreads();

    // ---- masked softmax: warp 0 -> token 0, warp 1 -> token 1 ----
    if (wid < 2) {
        const int tk = wid;
        const float* logit = (const float*)(smem + SM_LOG);
        const float v0 = valid[(size_t)(bn2 * 2 + tk) * Yd + lane];
        const float v1 = valid[(size_t)(bn2 * 2 + tk) * Yd + lane + 32];
        float l0 = (v0 < 0.5f) ? -10000.0f : logit[tk * 64 + lane];
        float l1 = (v1 < 0.5f) ? -10000.0f : logit[tk * 64 + lane + 32];

        float m = fmaxf(l0, l1);
        #pragma unroll
        for (int off = 16; off > 0; off >>= 1)
            m = fmaxf(m, __shfl_xor_sync(0xffffffffu, m, off));
        float e0 = expf(l0 - m), e1 = expf(l1 - m);
        float s = e0 + e1;
        #pragma unroll
        for (int off = 16; off > 0; off >>= 1)
            s += __shfl_xor_sync(0xffffffffu, s, off);
        float p0 = (e0 / s) * v0;
        float p1 = (e1 / s) * v1;
        float s2 = p0 + p1;
        #pragma unroll
        for (int off = 16; off > 0; off >>= 1)
            s2 += __shfl_xor_sync(0xffffffffu, s2, off);
        const float inv = 1.0f / fmaxf(s2, 1e-6f);
        ((float*)(smem + SM_WGT))[tk * 64 + lane]      = p0 * inv;
        ((float*)(smem + SM_WGT))[tk * 64 + lane + 32] = p1 * inv;
    }
    __syncthreads();

    // ---- aggregation: one output element per thread; re-read sampled f32 (L2-hot) ----
    {
        const float* wgt = (const float*)(smem + SM_WGT) + (tid >> 8) * 64;
        const int t = tid >> 8, c = tid & 255;
        const float* sp = sampled + ((size_t)(bn2 * 2 + t) * Yd) * Cd + c;
        float o = 0.f;
        #pragma unroll 8
        for (int y = 0; y < Yd; y++)
            o = fmaf(wgt[y], sp[(size_t)y * Cd], o);
        out[(size_t)(bn2 * 2 + t) * Cd + c] = o;
    }
}

extern "C" void kernel_launch(void* const* d_in, const int* in_sizes, int n_in,
                              void* d_out, int out_size)
{
    const float* sampled = (const float*)d_in[0];
    const float* valid   = (const float*)d_in[1];
    const float* y_norm  = (const float*)d_in[2];
    const float* W1      = (const float*)d_in[3];
    const float* b1      = (const float*)d_in[4];
    const float* W2      = (const float*)d_in[5];
    const float* b2      = (const float*)d_in[6];
    float* out = (float*)d_out;

    pack_w1_kernel<<<64, 256>>>(W1);
    cudaFuncSetAttribute(dat_mma7_kernel, cudaFuncAttributeMaxDynamicSharedMemorySize, SMEM_TOTAL);
    dat_mma7_kernel<<<CTAS, THREADS, SMEM_TOTAL>>>(sampled, valid, y_norm, W1, b1, W2, b2, out);
}

// round 14
// speedup vs baseline: 2.0921x; 1.2528x over previous
#include <cuda_runtime.h>
#include <cuda_fp16.h>
#include <cstdint>

// DepthAwareTokenAggregator via mma.sync fp16 (sm_80 ISA; tanh.approx needs sm_75+).
// B=8, N=512, Y=64, C=256. 2 tokens/CTA: M=128, K=256, N=256 (2 passes of 128).
// 512 threads (16 warps, 32x32 warp tile), 2 CTAs/SM.
// R9 structure exactly; single change: gelu via hardware tanh.approx.f32.

#define Yd 64
#define Cd 256
#define THREADS 512
#define CTAS 2048

// ---- smem byte offsets ----
#define SM_YN    0        // 64 f32
#define SM_B1    256      // 256 f32
#define SM_W2    1280     // 256 f32
#define SM_W1L   2304     // 256 f32 (W1 row 256: y_norm feature row)
#define SM_LP    3328     // 4 x 128 f32 logit partials
#define SM_LOG   5376     // 128 f32
#define SM_WGT   5888     // 128 f32
#define SM_A     6400     // 128 rows x 264 fp16 (stride 528B) = 67584
#define SM_B     73984    // 2 bufs x 18432 (128 n x 72 k fp16, stride 144B)
#define SMEM_TOTAL 110848

#define A_STRIDE 528
#define B_STRIDE 144      // 64 fp16 (128B) + 16B pad
#define BCHUNK   18432

// prepacked W1 fp16: [2 pass][4 chunk][128 n][64 k]
__device__ __half w1pack[2 * 4 * 128 * 64];

static __device__ __forceinline__ uint32_t smem_u32(const void* p) {
    uint32_t a;
    asm("{ .reg .u64 t; cvta.to.shared.u64 t, %1; cvt.u32.u64 %0, t; }" : "=r"(a) : "l"(p));
    return a;
}

static __device__ __forceinline__ void ldsm4(uint32_t* r, uint32_t addr) {
    asm volatile("ldmatrix.sync.aligned.m8n8.x4.shared.b16 {%0,%1,%2,%3}, [%4];"
                 : "=r"(r[0]), "=r"(r[1]), "=r"(r[2]), "=r"(r[3]) : "r"(addr));
}

static __device__ __forceinline__ void mma16816(float* d, const uint32_t* a,
                                                uint32_t b0, uint32_t b1) {
    asm volatile(
        "mma.sync.aligned.m16n8k16.row.col.f32.f16.f16.f32 "
        "{%0,%1,%2,%3}, {%4,%5,%6,%7}, {%8,%9}, {%0,%1,%2,%3};"
        : "+f"(d[0]), "+f"(d[1]), "+f"(d[2]), "+f"(d[3])
        : "r"(a[0]), "r"(a[1]), "r"(a[2]), "r"(a[3]), "r"(b0), "r"(b1));
}

#define CP_ASYNC16(dst, src) \
    asm volatile("cp.async.cg.shared.global [%0], [%1], 16;" :: "r"(dst), "l"(src) : "memory")
#define CP_COMMIT() asm volatile("cp.async.commit_group;" ::: "memory")
#define CP_WAIT1()  asm volatile("cp.async.wait_group 1;" ::: "memory")
#define CP_WAIT0()  asm volatile("cp.async.wait_group 0;" ::: "memory")

// tanh-form gelu with hardware tanh.approx.f32 (1 MUFU): ~7 issues total.
// |gelu_tanh - gelu_erf| <= ~5e-4 abs; tanh.approx err ~1e-3 abs worst.
// Only perturbs softmax logits (output rebuilt from exact fp32 sampled).
static __device__ __forceinline__ float gelu_tanh(float x) {
    float x3 = x * x * x;
    float arg = fmaf(0.044715f, x3, x) * 0.7978845608028654f;
    float t;
    asm("tanh.approx.f32 %0, %1;" : "=f"(t) : "f"(arg));
    return 0.5f * x * (1.0f + t);
}

// ---- pre-kernel: pack W1 (f32 [257,256]) -> fp16 chunk blocks ----
__global__ void pack_w1_kernel(const float* __restrict__ W1) {
    int gid = blockIdx.x * blockDim.x + threadIdx.x;   // 0..16383
    #pragma unroll
    for (int it = 0; it < 4; it++) {
        int e = gid + it * 16384;                      // 0..65535
        int p = e >> 15;
        int rem = e & 32767;
        int k = rem >> 7;                              // 0..255
        int n = rem & 127;
        int c = k >> 6, kk = k & 63;
        float x = W1[(size_t)k * Cd + p * 128 + n];
        w1pack[(size_t)(p * 4 + c) * 8192 + n * 64 + kk] = __float2half_rn(x);
    }
}

static __device__ __forceinline__ void issue_chunk(uint32_t sbase, int tid, int i) {
    const uint32_t dstb = sbase + SM_B + (i & 1) * BCHUNK;
    const __half* srcb = w1pack + (size_t)i * 8192;
    #pragma unroll
    for (int j = 0; j < 2; j++) {
        int idx16 = tid * 2 + j;                       // 0..1023
        int n = idx16 >> 3, ko = idx16 & 7;
        uint32_t dst = dstb + n * B_STRIDE + ko * 16;
        const void* src = srcb + idx16 * 8;
        CP_ASYNC16(dst, src);
    }
}

static __device__ __forceinline__ void epilogue_pass(
    float acc[2][4][4], float* lp, int p, const char* smem, int lane, int m0, int n0w)
{
    const float* b1s  = (const float*)(smem + SM_B1);
    const float* w2s  = (const float*)(smem + SM_W2);
    const float* w1ls = (const float*)(smem + SM_W1L);
    const float* yns  = (const float*)(smem + SM_YN);
    float yl[8], bb[8], ww[8];
    #pragma unroll
    for (int nt = 0; nt < 4; nt++)
        #pragma unroll
        for (int eb = 0; eb < 2; eb++) {
            int n = p * 128 + n0w + nt * 8 + 2 * (lane & 3) + eb;
            yl[nt * 2 + eb] = w1ls[n];
            bb[nt * 2 + eb] = b1s[n];
            ww[nt * 2 + eb] = w2s[n];
        }
    #pragma unroll
    for (int mt = 0; mt < 2; mt++)
        #pragma unroll
        for (int h = 0; h < 2; h++) {
            int row = m0 + mt * 16 + h * 8 + (lane >> 2);
            float yn = yns[row & 63];
            float s = 0.f;
            #pragma unroll
            for (int nt = 0; nt < 4; nt++)
                #pragma unroll
                for (int eb = 0; eb < 2; eb++) {
                    float x = acc[mt][nt][h * 2 + eb] + yn * yl[nt * 2 + eb] + bb[nt * 2 + eb];
                    s += gelu_tanh(x) * ww[nt * 2 + eb];
                }
            lp[mt * 2 + h] += s;
        }
}

__global__ __launch_bounds__(THREADS, 2)
void dat_mma8_kernel(const float* __restrict__ sampled,
                     const float* __restrict__ valid,
                     const float* __restrict__ y_norm,
                     const float* __restrict__ W1,
                     const float* __restrict__ b1,
                     const float* __restrict__ W2,
                     const float* __restrict__ b2,
                     float* __restrict__ out)
{
    extern __shared__ char smem[];
    const uint32_t sbase = smem_u32(smem);
    const int tid  = threadIdx.x;
    const int wid  = tid >> 5;
    const int lane = tid & 31;
    const int bn2  = blockIdx.x;

    // warp tile: wm in {0..3} -> 32 m-rows, wn in {0..3} -> 32 n-cols
    const int wm = wid & 3, wn = wid >> 2;
    const int m0 = wm * 32, n0w = wn * 32;

    // B pipeline first so cp.async overlaps the A load/convert
    issue_chunk(sbase, tid, 0); CP_COMMIT();
    issue_chunk(sbase, tid, 1); CP_COMMIT();

    // small vectors
    if (tid < Yd) ((float*)(smem + SM_YN))[tid] = y_norm[tid];
    if (tid < Cd) {
        ((float*)(smem + SM_B1))[tid]  = b1[tid];
        ((float*)(smem + SM_W2))[tid]  = W2[tid];
        ((float*)(smem + SM_W1L))[tid] = W1[(size_t)Cd * Cd + tid];
    }

    // ---- A: 128 rows x 256 f32 -> fp16, padded row-major; affine pointers ----
    {
        const float4* src = (const float4*)(sampled + (size_t)bn2 * (2 * Yd * Cd)) + tid;
        char* dst = smem + SM_A + (tid >> 6) * A_STRIDE + (tid & 63) * 8;
        #pragma unroll
        for (int i = 0; i < 16; i++) {
            float4 v = *src;
            __half2 h01 = __floats2half2_rn(v.x, v.y);
            __half2 h23 = __floats2half2_rn(v.z, v.w);
            *(uint2*)dst = make_uint2(*(uint32_t*)&h01, *(uint32_t*)&h23);
            src += THREADS;
            dst += 8 * A_STRIDE;   // 512 threads cover 8 rows per step
        }
    }

    float acc[2][4][4];
    #pragma unroll
    for (int mt = 0; mt < 2; mt++)
        #pragma unroll
        for (int nt = 0; nt < 4; nt++)
            #pragma unroll
            for (int e = 0; e < 4; e++) acc[mt][nt][e] = 0.f;
    float lp[4] = {0.f, 0.f, 0.f, 0.f};

    // hoisted smem bases
    const uint32_t abase = sbase + SM_A
        + (uint32_t)((m0 + (lane & 15)) * A_STRIDE + ((lane & 16) >> 1) * 2);
    const uint32_t blane = (uint32_t)((n0w + (lane & 7) + ((lane & 16) >> 1)) * B_STRIDE
                                      + (lane & 8) * 2);

    // ---- main loop: 8 chunks (pass = i>>2, k-chunk = i&3, 64 k each) ----
    #pragma unroll
    for (int i = 0; i < 8; i++) {
        if (i < 7) { CP_WAIT1(); } else { CP_WAIT0(); }
        __syncthreads();

        const uint32_t buf = sbase + SM_B + (i & 1) * BCHUNK + blane;
        const int kbase = (i & 3) * 64;

        #pragma unroll
        for (int kk = 0; kk < 4; kk++) {
            const int kglob = kbase + kk * 16;
            uint32_t a_[2][4];
            ldsm4(a_[0], abase + kglob * 2);
            ldsm4(a_[1], abase + kglob * 2 + 16 * A_STRIDE);
            uint32_t bf[2][4];
            ldsm4(bf[0], buf + kk * 32);
            ldsm4(bf[1], buf + kk * 32 + 16 * B_STRIDE);
            #pragma unroll
            for (int mt = 0; mt < 2; mt++)
                #pragma unroll
                for (int q = 0; q < 2; q++)
                    #pragma unroll
                    for (int h = 0; h < 2; h++)
                        mma16816(acc[mt][q * 2 + h], a_[mt], bf[q][2 * h], bf[q][2 * h + 1]);
        }

        if (i == 3) {
            epilogue_pass(acc, lp, 0, smem, lane, m0, n0w);
            #pragma unroll
            for (int mt = 0; mt < 2; mt++)
                #pragma unroll
                for (int nt = 0; nt < 4; nt++)
                    #pragma unroll
                    for (int e = 0; e < 4; e++) acc[mt][nt][e] = 0.f;
        }
        __syncthreads();
        if (i + 2 < 8) { issue_chunk(sbase, tid, i + 2); CP_COMMIT(); }
    }
    epilogue_pass(acc, lp, 1, smem, lane, m0, n0w);

    // ---- reduce logits across the 4 lanes sharing a row, write per-wn partials ----
    #pragma unroll
    for (int i = 0; i < 4; i++) {
        lp[i] += __shfl_xor_sync(0xffffffffu, lp[i], 1);
        lp[i] += __shfl_xor_sync(0xffffffffu, lp[i], 2);
    }
    if ((lane & 3) == 0) {
        #pragma unroll
        for (int mt = 0; mt < 2; mt++)
            #pragma unroll
            for (int h = 0; h < 2; h++) {
                int row = m0 + mt * 16 + h * 8 + (lane >> 2);
                ((float*)(smem + SM_LP))[wn * 128 + row] = lp[mt * 2 + h];
            }
    }
    __syncthreads();

    if (tid < 128) {
        const float* lps = (const float*)(smem + SM_LP);
        ((float*)(smem + SM_LOG))[tid] =
            lps[tid] + lps[128 + tid] + lps[256 + tid] + lps[384 + tid] + __ldg(b2);
    }
    __syncthreads();

    // ---- masked softmax: warp 0 -> token 0, warp 1 -> token 1 ----
    if (wid < 2) {
        const int tk = wid;
        const float* logit = (const float*)(smem + SM_LOG);
        const float v0 = valid[(size_t)(bn2 * 2 + tk) * Yd + lane];
        const float v1 = valid[(size_t)(bn2 * 2 + tk) * Yd + lane + 32];
        float l0 = (v0 < 0.5f) ? -10000.0f : logit[tk * 64 + lane];
        float l1 = (v1 < 0.5f) ? -10000.0f : logit[tk * 64 + lane + 32];

        float m = fmaxf(l0, l1);
        #pragma unroll
        for (int off = 16; off > 0; off >>= 1)
            m = fmaxf(m, __shfl_xor_sync(0xffffffffu, m, off));
        float e0 = expf(l0 - m), e1 = expf(l1 - m);
        float s = e0 + e1;
        #pragma unroll
        for (int off = 16; off > 0; off >>= 1)
            s += __shfl_xor_sync(0xffffffffu, s, off);
        float p0 = (e0 / s) * v0;
        float p1 = (e1 / s) * v1;
        float s2 = p0 + p1;
        #pragma unroll
        for (int off = 16; off > 0; off >>= 1)
            s2 += __shfl_xor_sync(0xffffffffu, s2, off);
        const float inv = 1.0f / fmaxf(s2, 1e-6f);
        ((float*)(smem + SM_WGT))[tk * 64 + lane]      = p0 * inv;
        ((float*)(smem + SM_WGT))[tk * 64 + lane + 32] = p1 * inv;
    }
    __syncthreads();

    // ---- aggregation: one output element per thread; re-read sampled f32 (L2-hot) ----
    {
        const float* wgt = (const float*)(smem + SM_WGT) + (tid >> 8) * 64;
        const int t = tid >> 8, c = tid & 255;
        const float* sp = sampled + ((size_t)(bn2 * 2 + t) * Yd) * Cd + c;
        float o = 0.f;
        #pragma unroll 8
        for (int y = 0; y < Yd; y++)
            o = fmaf(wgt[y], sp[(size_t)y * Cd], o);
        out[(size_t)(bn2 * 2 + t) * Cd + c] = o;
    }
}

extern "C" void kernel_launch(void* const* d_in, const int* in_sizes, int n_in,
                              void* d_out, int out_size)
{
    const float* sampled = (const float*)d_in[0];
    const float* valid   = (const float*)d_in[1];
    const float* y_norm  = (const float*)d_in[2];
    const float* W1      = (const float*)d_in[3];
    const float* b1      = (const float*)d_in[4];
    const float* W2      = (const float*)d_in[5];
    const float* b2      = (const float*)d_in[6];
    float* out = (float*)d_out;

    pack_w1_kernel<<<64, 256>>>(W1);
    cudaFuncSetAttribute(dat_mma8_kernel, cudaFuncAttributeMaxDynamicSharedMemorySize, SMEM_TOTAL);
    dat_mma8_kernel<<<CTAS, THREADS, SMEM_TOTAL>>>(sampled, valid, y_norm, W1, b1, W2, b2, out);
}